// round 1
// baseline (speedup 1.0000x reference)
#include <cuda_runtime.h>
#include <cstddef>

// Problem constants
#define NN 512          // nodes
#define HD 1024         // hidden dim
#define NE 16384        // edges
#define KR 144          // padded Hmat rows (128 S + 4 bias2 + 12 zero pad)

// ---------------- scratch (device globals; no allocation allowed) ----------
__device__ __align__(16) float g_Hmat[KR * HD];        // rows 0..127 = S, 128..131 = bias2, rest 0
__device__ __align__(16) float g_attC[NN * KR];        // folded attention (512 x 144)
__device__ __align__(16) float g_hp[NN * HD];          // h_prime (512 x 1024)
__device__ __align__(16) float g_att[NN * NN];
__device__ __align__(16) float g_adj2[NN * NN];
__device__ int      g_last[NN * NN];
__device__ float    g_SS1[132];
__device__ float    g_SS2[132];
__device__ float    g_outraw[NN + 1];
__device__ unsigned g_amax;

// ---------------- init ------------------------------------------------------
__global__ void k_init() {
    int idx = blockIdx.x * blockDim.x + threadIdx.x;
    if (idx < NN * NN)  g_last[idx] = -1;
    if (idx < KR * HD)  g_Hmat[idx] = 0.f;
    if (idx < NN + 1)   g_outraw[idx] = 0.f;
    if (idx == 0)       g_amax = 0u;
}

// ---------------- scatter: last-edge-wins per dense cell --------------------
__global__ void k_scatter(const int* __restrict__ er, const int* __restrict__ ec) {
    int k = blockIdx.x * blockDim.x + threadIdx.x;
    if (k < NE) atomicMax(&g_last[er[k] * NN + ec[k]], k);
}

// ---------------- bias2[b,j] = sum_kappa img[b, kappa%1024] * W[kappa, j] ---
__global__ void k_bias2(const float* __restrict__ W, const float* __restrict__ img) {
    int j  = blockIdx.x * 128 + threadIdx.x;   // grid.x = 8
    int r0 = blockIdx.y * 128;                 // grid.y = 32 (rho chunks)
    float a0 = 0.f, a1 = 0.f, a2 = 0.f, a3 = 0.f;
    #pragma unroll 4
    for (int rr = 0; rr < 128; rr++) {
        int rho = r0 + rr;
        float w = W[(size_t)rho * HD + j];
        int d = rho & 1023;
        a0 += img[d]          * w;
        a1 += img[1024 + d]   * w;
        a2 += img[2048 + d]   * w;
        a3 += img[3072 + d]   * w;
    }
    atomicAdd(&g_Hmat[(size_t)(128) * HD + j], a0);
    atomicAdd(&g_Hmat[(size_t)(129) * HD + j], a1);
    atomicAdd(&g_Hmat[(size_t)(130) * HD + j], a2);
    atomicAdd(&g_Hmat[(size_t)(131) * HD + j], a3);
}

// ---------------- generic 64x64 SGEMM body (256 thr, 4x4 micro) -------------
template<bool ATOMIC>
__device__ __forceinline__ void sgemm_body(
    const float* __restrict__ A, int lda,
    const float* __restrict__ B, int ldb,
    float* __restrict__ C, int ldc,
    int kBase, int kLen)
{
    __shared__ float As[16][64];   // transposed: As[k][m]
    __shared__ float Bs[16][64];
    const int tid = threadIdx.x;
    const int tx = tid & 15, ty = tid >> 4;
    const int brow = blockIdx.y * 64;
    const int bcol = blockIdx.x * 64;
    const int a_row = tid >> 2;
    const int a_col = (tid & 3) << 2;
    const int b_row = tid >> 4;
    const int b_col = (tid & 15) << 2;
    float acc[4][4] = {};
    for (int k0 = 0; k0 < kLen; k0 += 16) {
        float4 av = *reinterpret_cast<const float4*>(
            &A[(size_t)(brow + a_row) * lda + kBase + k0 + a_col]);
        As[a_col + 0][a_row] = av.x;
        As[a_col + 1][a_row] = av.y;
        As[a_col + 2][a_row] = av.z;
        As[a_col + 3][a_row] = av.w;
        *reinterpret_cast<float4*>(&Bs[b_row][b_col]) =
            *reinterpret_cast<const float4*>(
                &B[(size_t)(kBase + k0 + b_row) * ldb + bcol + b_col]);
        __syncthreads();
        #pragma unroll
        for (int k = 0; k < 16; k++) {
            float4 a4 = *reinterpret_cast<const float4*>(&As[k][ty << 2]);
            float4 b4 = *reinterpret_cast<const float4*>(&Bs[k][tx << 2]);
            float ar[4] = {a4.x, a4.y, a4.z, a4.w};
            float br[4] = {b4.x, b4.y, b4.z, b4.w};
            #pragma unroll
            for (int i = 0; i < 4; i++)
                #pragma unroll
                for (int j = 0; j < 4; j++)
                    acc[i][j] += ar[i] * br[j];
        }
        __syncthreads();
    }
    #pragma unroll
    for (int i = 0; i < 4; i++)
        #pragma unroll
        for (int j = 0; j < 4; j++) {
            int r = brow + (ty << 2) + i;
            int c = bcol + (tx << 2) + j;
            if (ATOMIC) atomicAdd(&C[(size_t)r * ldc + c], acc[i][j]);
            else        C[(size_t)r * ldc + c] = acc[i][j];
        }
}

// S = reshape(X,(128,4096)) @ W  -> Hmat rows 0..127 (split-K over blockIdx.z)
__global__ void k_gemmS(const float* __restrict__ X, const float* __restrict__ W) {
    sgemm_body<true>(X, 4096, W, HD, g_Hmat, HD, blockIdx.z * 1024, 1024);
}

// hp = attC(512x144) @ Hmat(144x1024)
__global__ void k_gemmHP() {
    sgemm_body<false>(g_attC, KR, g_Hmat, HD, g_hp, HD, 0, KR);
}

// ---------------- SS1/SS2: Hmat row dot a[:H], a[H:] ------------------------
__global__ void k_rowdot(const float* __restrict__ avec) {
    __shared__ float red[8];
    int row = blockIdx.x;          // 0..131
    int t = threadIdx.x;           // 256
    const float* hrow = &g_Hmat[(size_t)row * HD];
    float p1 = 0.f, p2 = 0.f;
    for (int j = t; j < HD; j += 256) {
        float h = hrow[j];
        p1 += h * avec[j];
        p2 += h * avec[HD + j];
    }
    for (int o = 16; o > 0; o >>= 1) p1 += __shfl_down_sync(0xffffffffu, p1, o);
    if ((t & 31) == 0) red[t >> 5] = p1;
    __syncthreads();
    if (t == 0) { float s = 0; for (int w = 0; w < 8; w++) s += red[w]; g_SS1[row] = s; }
    __syncthreads();
    for (int o = 16; o > 0; o >>= 1) p2 += __shfl_down_sync(0xffffffffu, p2, o);
    if ((t & 31) == 0) red[t >> 5] = p2;
    __syncthreads();
    if (t == 0) { float s = 0; for (int w = 0; w < 8; w++) s += red[w]; g_SS2[row] = s; }
}

// ---------------- softmax row + attC fold + amax ----------------------------
__global__ void k_softmax(const float* __restrict__ adj_vals) {
    __shared__ float sh[NN];
    int n = blockIdx.x, c = threadIdx.x;   // 512 threads
    int le = g_last[n * NN + c];
    float s1n = g_SS1[n & 127] + g_SS1[128 + (n >> 7)];
    float ev = 0.f, adv = 0.f;
    if (le >= 0) {
        float x = s1n + g_SS2[c & 127] + g_SS2[128 + (c >> 7)];
        ev = (x > 0.f) ? x : 0.2f * x;     // leaky_relu 0.2
        adv = 2.f * adj_vals[le];
    }
    g_adj2[n * NN + c] = adv;
    // row max (structural zeros included)
    sh[c] = ev; __syncthreads();
    for (int s = 256; s > 0; s >>= 1) { if (c < s) sh[c] = fmaxf(sh[c], sh[c + s]); __syncthreads(); }
    float m = sh[0]; __syncthreads();
    float p = expf(ev - m);
    sh[c] = p; __syncthreads();
    for (int s = 256; s > 0; s >>= 1) { if (c < s) sh[c] += sh[c + s]; __syncthreads(); }
    float Z = sh[0]; __syncthreads();
    float att = p / Z;
    g_att[n * NN + c] = att;
    sh[c] = att; __syncthreads();
    if (c < 128) {
        g_attC[(size_t)n * KR + c] = sh[c] + sh[c + 128] + sh[c + 256] + sh[c + 384];
    } else if (c < 132) {
        int b = c - 128;
        float s = 0.f;
        for (int i = 0; i < 128; i++) s += sh[b * 128 + i];
        g_attC[(size_t)n * KR + c] = s;
    } else if (c < KR) {
        g_attC[(size_t)n * KR + c] = 0.f;  // padding cols
    }
    __syncthreads();
    // amax over set cells (all values >= 0 -> bitwise max valid)
    sh[c] = adv; __syncthreads();
    for (int s = 256; s > 0; s >>= 1) { if (c < s) sh[c] = fmaxf(sh[c], sh[c + s]); __syncthreads(); }
    if (c == 0) atomicMax(&g_amax, __float_as_uint(sh[0]));
}

// ---------------- new_adj = att * adj2 / amax   (amin == 0 structurally) ----
__global__ void k_newadj(float* __restrict__ outp) {
    int idx = blockIdx.x * blockDim.x + threadIdx.x;
    if (idx < NN * NN) {
        float amax = __uint_as_float(g_amax);
        outp[idx] = g_att[idx] * (g_adj2[idx] / amax);
    }
}

// ---------------- out_raw[i] = lin_w[i,:] . hp_flat  (HBM-bound, 1.08 GB) ---
__global__ void k_matvec(const float* __restrict__ lin_w) {
    __shared__ float red[8];
    int i   = blockIdx.y;              // 0..512
    int seg = blockIdx.x;              // 0..15
    const int SEG = (NN * HD) / 16;    // 32768
    size_t base = (size_t)i * (NN * HD) + (size_t)seg * SEG;
    const float4* wp4 = reinterpret_cast<const float4*>(lin_w + base);
    const float4* vp4 = reinterpret_cast<const float4*>(g_hp + seg * SEG);
    int t = threadIdx.x;               // 256
    float s = 0.f;
    #pragma unroll 4
    for (int idx = t; idx < SEG / 4; idx += 256) {
        float4 w = wp4[idx];
        float4 v = vp4[idx];
        s += w.x * v.x + w.y * v.y + w.z * v.z + w.w * v.w;
    }
    for (int o = 16; o > 0; o >>= 1) s += __shfl_down_sync(0xffffffffu, s, o);
    if ((t & 31) == 0) red[t >> 5] = s;
    __syncthreads();
    if (t == 0) {
        float tot = 0.f;
        for (int w = 0; w < 8; w++) tot += red[w];
        atomicAdd(&g_outraw[i], tot);
    }
}

// ---------------- final min-max normalize of 513 outputs --------------------
__global__ void k_final(const float* __restrict__ lin_b, float* __restrict__ outp) {
    __shared__ float red[16];
    __shared__ float s_mn, s_mx;
    int t = threadIdx.x;               // 512 threads
    float v0 = g_outraw[t] + lin_b[t];
    bool has2 = (t == 0);
    float v1 = has2 ? (g_outraw[NN] + lin_b[NN]) : 0.f;
    float mn = v0, mx = v0;
    if (has2) { mn = fminf(mn, v1); mx = fmaxf(mx, v1); }
    // min
    float r = mn;
    for (int o = 16; o > 0; o >>= 1) r = fminf(r, __shfl_down_sync(0xffffffffu, r, o));
    if ((t & 31) == 0) red[t >> 5] = r;
    __syncthreads();
    if (t < 32) {
        r = (t < 16) ? red[t] : red[0];
        for (int o = 8; o > 0; o >>= 1) r = fminf(r, __shfl_down_sync(0xffffffffu, r, o));
        if (t == 0) s_mn = r;
    }
    __syncthreads();
    // max
    r = mx;
    for (int o = 16; o > 0; o >>= 1) r = fmaxf(r, __shfl_down_sync(0xffffffffu, r, o));
    if ((t & 31) == 0) red[t >> 5] = r;
    __syncthreads();
    if (t < 32) {
        r = (t < 16) ? red[t] : red[0];
        for (int o = 8; o > 0; o >>= 1) r = fmaxf(r, __shfl_down_sync(0xffffffffu, r, o));
        if (t == 0) s_mx = r;
    }
    __syncthreads();
    float mnv = s_mn;
    float den = s_mx - s_mn;
    if (den == 0.f) {
        outp[t] = 0.5f;
        if (has2) outp[NN] = 0.5f;
    } else {
        outp[t] = (v0 - mnv) / den;
        if (has2) outp[NN] = (v1 - mnv) / den;
    }
}

// ---------------- launcher ---------------------------------------------------
extern "C" void kernel_launch(void* const* d_in, const int* in_sizes, int n_in,
                              void* d_out, int out_size) {
    (void)in_sizes; (void)n_in; (void)out_size;
    const float* img   = (const float*)d_in[0];   // (4,1024)
    const int*   erow  = (const int*)  d_in[1];   // (16384,)
    const int*   ecol  = (const int*)  d_in[2];   // (16384,)
    const float* adjv  = (const float*)d_in[3];   // (16384,)
    const float* X     = (const float*)d_in[4];   // (512,1024)
    const float* W     = (const float*)d_in[5];   // (4096,1024)
    const float* avec  = (const float*)d_in[6];   // (2048,1)
    const float* linw  = (const float*)d_in[7];   // (513, 524288)
    const float* linb  = (const float*)d_in[8];   // (513,)
    float* out = (float*)d_out;                   // 262144 new_adj + 513 normalized

    k_init<<<1024, 256>>>();
    k_scatter<<<64, 256>>>(erow, ecol);
    k_bias2<<<dim3(8, 32), 128>>>(W, img);
    k_gemmS<<<dim3(16, 2, 4), 256>>>(X, W);
    k_rowdot<<<132, 256>>>(avec);
    k_softmax<<<NN, NN>>>(adjv);
    k_newadj<<<1024, 256>>>(out);
    k_gemmHP<<<dim3(16, 8, 1), 256>>>();
    k_matvec<<<dim3(16, NN + 1), 256>>>(linw);
    k_final<<<1, NN>>>(linb, out + NN * NN);
}

// round 2
// speedup vs baseline: 1.2330x; 1.2330x over previous
#include <cuda_runtime.h>
#include <cstddef>

// Problem constants
#define NN 512          // nodes
#define HD 1024         // hidden dim
#define NE 16384        // edges
#define KR 144          // padded Hmat rows (128 S + 4 bias2 + 12 zero pad)
#define ZS 16           // split-K factor for gemmS

// ---------------- scratch (device globals; no allocation allowed) ----------
__device__ __align__(16) float g_Spart[ZS * 128 * HD];   // split-K partials for S
__device__ __align__(16) float g_b2part[32 * 4 * HD];    // bias2 partials (32 rho-chunks)
__device__ __align__(16) float g_Hmat[KR * HD];          // rows 0..127 = S, 128..131 = bias2, 132..143 stay 0 (never written)
__device__ __align__(16) float g_attC[NN * KR];          // folded attention (512 x 144)
__device__ __align__(16) float g_hp[NN * HD];            // h_prime (512 x 1024)
__device__ __align__(16) float g_attadj[NN * NN];        // att * adj2 (pre-division)
__device__ int      g_last[NN * NN];
__device__ float    g_SS1[132];
__device__ float    g_SS2[132];
__device__ float    g_outpart[(NN + 1) * 16];            // matvec partials (no atomics)
__device__ unsigned g_amax;

// ---------------- scatter: last-edge-wins per dense cell --------------------
__global__ void k_scatter(const int* __restrict__ er, const int* __restrict__ ec) {
    int k = blockIdx.x * blockDim.x + threadIdx.x;
    if (k < NE) atomicMax(&g_last[er[k] * NN + ec[k]], k);
}

// ---------------- bias2 partials: chunk rc of rho, 4 batch outputs ----------
__global__ void k_bias2(const float* __restrict__ W, const float* __restrict__ img) {
    int j  = blockIdx.x * 128 + threadIdx.x;   // grid.x = 8
    int rc = blockIdx.y;                       // 0..31
    int r0 = rc * 128;
    float a0 = 0.f, a1 = 0.f, a2 = 0.f, a3 = 0.f;
    #pragma unroll 4
    for (int rr = 0; rr < 128; rr++) {
        int rho = r0 + rr;
        float w = W[(size_t)rho * HD + j];
        int d = rho & 1023;
        a0 += img[d]        * w;
        a1 += img[1024 + d] * w;
        a2 += img[2048 + d] * w;
        a3 += img[3072 + d] * w;
    }
    g_b2part[(rc * 4 + 0) * HD + j] = a0;
    g_b2part[(rc * 4 + 1) * HD + j] = a1;
    g_b2part[(rc * 4 + 2) * HD + j] = a2;
    g_b2part[(rc * 4 + 3) * HD + j] = a3;
}

// ---------------- 64x64 SGEMM body, double-buffered smem, 4x4 micro ---------
__device__ __forceinline__ void sgemm64(
    const float* __restrict__ A, int lda,
    const float* __restrict__ B, int ldb,
    float* __restrict__ C, int ldc,
    int kBase, int kLen)
{
    __shared__ float As[2][16][64];   // transposed: As[buf][k][m]
    __shared__ float Bs[2][16][64];
    const int tid = threadIdx.x;
    const int tx = tid & 15, ty = tid >> 4;
    const int brow = blockIdx.y * 64;
    const int bcol = blockIdx.x * 64;
    const int a_row = tid >> 2;
    const int a_col = (tid & 3) << 2;
    const int b_row = tid >> 4;
    const int b_col = (tid & 15) << 2;

    const float* Aptr = &A[(size_t)(brow + a_row) * lda + kBase + a_col];
    const float* Bptr = &B[(size_t)(kBase + b_row) * ldb + bcol + b_col];

    float4 av = *reinterpret_cast<const float4*>(Aptr);
    float4 bv = *reinterpret_cast<const float4*>(Bptr);

    const int T = kLen >> 4;
    float acc[4][4] = {};

    As[0][a_col + 0][a_row] = av.x;
    As[0][a_col + 1][a_row] = av.y;
    As[0][a_col + 2][a_row] = av.z;
    As[0][a_col + 3][a_row] = av.w;
    *reinterpret_cast<float4*>(&Bs[0][b_row][b_col]) = bv;
    __syncthreads();

    int cur = 0;
    for (int t = 0; t < T; t++) {
        if (t + 1 < T) {
            av = *reinterpret_cast<const float4*>(Aptr + (t + 1) * 16);
            bv = *reinterpret_cast<const float4*>(Bptr + (size_t)(t + 1) * 16 * ldb);
        }
        #pragma unroll
        for (int k = 0; k < 16; k++) {
            float4 a4 = *reinterpret_cast<const float4*>(&As[cur][k][ty << 2]);
            float4 b4 = *reinterpret_cast<const float4*>(&Bs[cur][k][tx << 2]);
            float ar[4] = {a4.x, a4.y, a4.z, a4.w};
            float br[4] = {b4.x, b4.y, b4.z, b4.w};
            #pragma unroll
            for (int i = 0; i < 4; i++)
                #pragma unroll
                for (int j = 0; j < 4; j++)
                    acc[i][j] += ar[i] * br[j];
        }
        if (t + 1 < T) {
            int nxt = cur ^ 1;
            As[nxt][a_col + 0][a_row] = av.x;
            As[nxt][a_col + 1][a_row] = av.y;
            As[nxt][a_col + 2][a_row] = av.z;
            As[nxt][a_col + 3][a_row] = av.w;
            *reinterpret_cast<float4*>(&Bs[nxt][b_row][b_col]) = bv;
            __syncthreads();
            cur = nxt;
        }
    }
    #pragma unroll
    for (int i = 0; i < 4; i++) {
        int r = brow + (ty << 2) + i;
        float4 o;
        o.x = acc[i][0]; o.y = acc[i][1]; o.z = acc[i][2]; o.w = acc[i][3];
        *reinterpret_cast<float4*>(&C[(size_t)r * ldc + bcol + (tx << 2)]) = o;
    }
}

// S partials: g_Spart[z] = Xr[:, z*256:(z+1)*256] @ W[z*256:(z+1)*256, :]
__global__ void __launch_bounds__(256) k_gemmS(const float* __restrict__ X, const float* __restrict__ W) {
    sgemm64(X, 4096, W, HD, &g_Spart[(size_t)blockIdx.z * 128 * HD], HD,
            blockIdx.z * (4096 / ZS), 4096 / ZS);
}

// hp = attC(512x144) @ Hmat(144x1024)
__global__ void __launch_bounds__(256) k_gemmHP() {
    sgemm64(g_attC, KR, g_Hmat, HD, g_hp, HD, 0, KR);
}

// ---------------- reduce split-K partials + bias2 into Hmat -----------------
__global__ void k_reduceS() {
    int b = blockIdx.x;
    if (b < 512) {
        int idx = b * 256 + threadIdx.x;       // 0..131071
        float s = 0.f;
        #pragma unroll
        for (int z = 0; z < ZS; z++) s += g_Spart[z * 128 * HD + idx];
        g_Hmat[idx] = s;
    } else {
        int bb = b - 512;                      // batch 0..3
        for (int j = threadIdx.x; j < HD; j += 256) {
            float s = 0.f;
            #pragma unroll
            for (int r = 0; r < 32; r++) s += g_b2part[(r * 4 + bb) * HD + j];
            g_Hmat[(size_t)(128 + bb) * HD + j] = s;
        }
    }
}

// ---------------- SS1/SS2: Hmat row dot a[:H], a[H:] ------------------------
__global__ void k_rowdot(const float* __restrict__ avec) {
    __shared__ float red[8];
    int row = blockIdx.x;          // 0..131
    int t = threadIdx.x;           // 256
    const float* hrow = &g_Hmat[(size_t)row * HD];
    float p1 = 0.f, p2 = 0.f;
    for (int j = t; j < HD; j += 256) {
        float h = hrow[j];
        p1 += h * avec[j];
        p2 += h * avec[HD + j];
    }
    for (int o = 16; o > 0; o >>= 1) p1 += __shfl_down_sync(0xffffffffu, p1, o);
    if ((t & 31) == 0) red[t >> 5] = p1;
    __syncthreads();
    if (t == 0) { float s = 0; for (int w = 0; w < 8; w++) s += red[w]; g_SS1[row] = s; }
    __syncthreads();
    for (int o = 16; o > 0; o >>= 1) p2 += __shfl_down_sync(0xffffffffu, p2, o);
    if ((t & 31) == 0) red[t >> 5] = p2;
    __syncthreads();
    if (t == 0) { float s = 0; for (int w = 0; w < 8; w++) s += red[w]; g_SS2[row] = s; }
}

// ---------------- softmax row + attC fold + amax (warp-shuffle reductions) --
__global__ void __launch_bounds__(512) k_softmax(const float* __restrict__ adj_vals) {
    __shared__ float sw[16];       // per-warp p-sums (kept for b-fold)
    __shared__ float sa[16];
    __shared__ float sh[NN];
    __shared__ float s_m, s_Z;
    int n = blockIdx.x, c = threadIdx.x;   // 512 threads
    int w = c >> 5, l = c & 31;
    int le = g_last[n * NN + c];
    float s1n = g_SS1[n & 127] + g_SS1[128 + (n >> 7)];
    float ev = 0.f, adv = 0.f;
    if (le >= 0) {
        float x = s1n + g_SS2[c & 127] + g_SS2[128 + (c >> 7)];
        ev = (x > 0.f) ? x : 0.2f * x;     // leaky_relu 0.2
        adv = 2.f * adj_vals[le];
    }
    // row max
    float r = ev;
    for (int o = 16; o > 0; o >>= 1) r = fmaxf(r, __shfl_xor_sync(0xffffffffu, r, o));
    if (l == 0) sa[w] = r;
    __syncthreads();
    if (w == 0) {
        float m = sa[l & 15];
        for (int o = 8; o > 0; o >>= 1) m = fmaxf(m, __shfl_xor_sync(0xffffffffu, m, o));
        if (l == 0) s_m = m;
    }
    __syncthreads();
    float p = expf(ev - s_m);
    // row sum (per-warp sums preserved in sw[] for batch fold)
    r = p;
    for (int o = 16; o > 0; o >>= 1) r += __shfl_xor_sync(0xffffffffu, r, o);
    if (l == 0) sw[w] = r;
    __syncthreads();
    if (w == 0) {
        float z = (l < 16) ? sw[l] : 0.f;
        for (int o = 16; o > 0; o >>= 1) z += __shfl_xor_sync(0xffffffffu, z, o);
        if (l == 0) s_Z = z;
    }
    __syncthreads();
    float invZ = 1.f / s_Z;
    float att = p * invZ;
    g_attadj[n * NN + c] = att * adv;
    sh[c] = att;
    __syncthreads();
    if (c < 128) {
        g_attC[(size_t)n * KR + c] = sh[c] + sh[c + 128] + sh[c + 256] + sh[c + 384];
    } else if (c < 132) {
        int b = c - 128;   // attC[n,128+b] = sum of 128-chunk b = (4 warp p-sums)/Z
        g_attC[(size_t)n * KR + c] = (sw[4 * b] + sw[4 * b + 1] + sw[4 * b + 2] + sw[4 * b + 3]) * invZ;
    } else if (c < KR) {
        g_attC[(size_t)n * KR + c] = 0.f;
    }
    // amax over adv (all >= 0 -> bitwise max valid)
    r = adv;
    for (int o = 16; o > 0; o >>= 1) r = fmaxf(r, __shfl_xor_sync(0xffffffffu, r, o));
    if (l == 0) sa[w] = r;
    __syncthreads();
    if (c == 0) {
        float m = 0.f;
        for (int i = 0; i < 16; i++) m = fmaxf(m, sa[i]);
        atomicMax(&g_amax, __float_as_uint(m));
    }
}

// ---------------- new_adj = attadj / amax   (amin == 0 structurally) --------
__global__ void k_newadj(float* __restrict__ outp) {
    int idx = blockIdx.x * blockDim.x + threadIdx.x;
    float inv = 1.f / __uint_as_float(g_amax);
    if (idx < NN * NN) outp[idx] = g_attadj[idx] * inv;
}

// ---------------- out partials: lin_w[i,:] . hp_flat  (HBM-bound, 1.08 GB) --
__global__ void __launch_bounds__(256) k_matvec(const float* __restrict__ lin_w) {
    __shared__ float red[8];
    int i   = blockIdx.y;              // 0..512
    int seg = blockIdx.x;              // 0..15
    const int SEG = (NN * HD) / 16;    // 32768
    size_t base = (size_t)i * (NN * HD) + (size_t)seg * SEG;
    const float4* wp4 = reinterpret_cast<const float4*>(lin_w + base);
    const float4* vp4 = reinterpret_cast<const float4*>(g_hp + seg * SEG);
    int t = threadIdx.x;               // 256
    float s = 0.f;
    #pragma unroll 8
    for (int idx = t; idx < SEG / 4; idx += 256) {
        float4 w = __ldcs(wp4 + idx);      // streaming: keep hp resident in L2
        float4 v = vp4[idx];
        s += w.x * v.x + w.y * v.y + w.z * v.z + w.w * v.w;
    }
    for (int o = 16; o > 0; o >>= 1) s += __shfl_down_sync(0xffffffffu, s, o);
    if ((t & 31) == 0) red[t >> 5] = s;
    __syncthreads();
    if (t == 0) {
        float tot = 0.f;
        for (int w = 0; w < 8; w++) tot += red[w];
        g_outpart[i * 16 + seg] = tot;
    }
}

// ---------------- final: sum partials, min-max normalize 513 outputs --------
__global__ void k_final(const float* __restrict__ lin_b, float* __restrict__ outp) {
    __shared__ float red[16];
    __shared__ float s_mn, s_mx;
    int t = threadIdx.x;               // 512 threads
    float v0 = lin_b[t];
    #pragma unroll
    for (int s = 0; s < 16; s++) v0 += g_outpart[t * 16 + s];
    bool has2 = (t == 0);
    float v1 = 0.f;
    if (has2) {
        v1 = lin_b[NN];
        for (int s = 0; s < 16; s++) v1 += g_outpart[NN * 16 + s];
    }
    float mn = v0, mx = v0;
    if (has2) { mn = fminf(mn, v1); mx = fmaxf(mx, v1); }
    float r = mn;
    for (int o = 16; o > 0; o >>= 1) r = fminf(r, __shfl_down_sync(0xffffffffu, r, o));
    if ((t & 31) == 0) red[t >> 5] = r;
    __syncthreads();
    if (t < 32) {
        r = (t < 16) ? red[t] : red[0];
        for (int o = 8; o > 0; o >>= 1) r = fminf(r, __shfl_down_sync(0xffffffffu, r, o));
        if (t == 0) s_mn = r;
    }
    __syncthreads();
    r = mx;
    for (int o = 16; o > 0; o >>= 1) r = fmaxf(r, __shfl_down_sync(0xffffffffu, r, o));
    if ((t & 31) == 0) red[t >> 5] = r;
    __syncthreads();
    if (t < 32) {
        r = (t < 16) ? red[t] : red[0];
        for (int o = 8; o > 0; o >>= 1) r = fmaxf(r, __shfl_down_sync(0xffffffffu, r, o));
        if (t == 0) s_mx = r;
    }
    __syncthreads();
    float mnv = s_mn;
    float den = s_mx - s_mn;
    if (den == 0.f) {
        outp[t] = 0.5f;
        if (has2) outp[NN] = 0.5f;
    } else {
        outp[t] = (v0 - mnv) / den;
        if (has2) outp[NN] = (v1 - mnv) / den;
    }
}

// ---------------- launcher ---------------------------------------------------
extern "C" void kernel_launch(void* const* d_in, const int* in_sizes, int n_in,
                              void* d_out, int out_size) {
    (void)in_sizes; (void)n_in; (void)out_size;
    const float* img   = (const float*)d_in[0];   // (4,1024)
    const int*   erow  = (const int*)  d_in[1];   // (16384,)
    const int*   ecol  = (const int*)  d_in[2];   // (16384,)
    const float* adjv  = (const float*)d_in[3];   // (16384,)
    const float* X     = (const float*)d_in[4];   // (512,1024)
    const float* W     = (const float*)d_in[5];   // (4096,1024)
    const float* avec  = (const float*)d_in[6];   // (2048,1)
    const float* linw  = (const float*)d_in[7];   // (513, 524288)
    const float* linb  = (const float*)d_in[8];   // (513,)
    float* out = (float*)d_out;                   // 262144 new_adj + 513 normalized

    void* p_last = nullptr;  cudaGetSymbolAddress(&p_last, g_last);
    void* p_amax = nullptr;  cudaGetSymbolAddress(&p_amax, g_amax);
    cudaMemsetAsync(p_last, 0xFF, (size_t)NN * NN * sizeof(int), 0);  // -1
    cudaMemsetAsync(p_amax, 0x00, sizeof(unsigned), 0);

    k_scatter<<<64, 256>>>(erow, ecol);
    k_bias2<<<dim3(8, 32), 128>>>(W, img);
    k_gemmS<<<dim3(16, 2, ZS), 256>>>(X, W);
    k_reduceS<<<516, 256>>>();
    k_rowdot<<<132, 256>>>(avec);
    k_softmax<<<NN, NN>>>(adjv);
    k_newadj<<<1024, 256>>>(out);
    k_gemmHP<<<dim3(16, 8, 1), 256>>>();
    k_matvec<<<dim3(16, NN + 1), 256>>>(linw);
    k_final<<<1, NN>>>(linb, out + NN * NN);
}

// round 4
// speedup vs baseline: 1.2457x; 1.0103x over previous
#include <cuda_runtime.h>
#include <cstddef>

// Problem constants
#define NN 512          // nodes
#define HD 1024         // hidden dim
#define NE 16384        // edges
#define KR 144          // padded Hmat rows (128 S + 4 bias2 + 12 zero pad)
#define ZS 16           // split-K factor for gemmS

// ---------------- scratch (device globals; no allocation allowed) ----------
__device__ __align__(16) float g_Spart[ZS * 128 * HD];   // split-K partials for S
__device__ __align__(16) float g_b2part[32 * 4 * HD];    // bias2 partials
__device__ __align__(16) float g_Hmat[KR * HD];          // 0..127 S, 128..131 bias2, 132..143 stay 0
__device__ __align__(16) float g_attC[NN * KR];          // folded attention (512 x 144)
__device__ __align__(16) float g_hp[NN * HD];            // h_prime (512 x 1024)
__device__ int      g_last[NN * NN];
__device__ float    g_SS1[132];
__device__ float    g_SS2[132];
__device__ float    g_outpart[(NN + 1) * 16];            // matvec partials
__device__ unsigned g_amax;

// ---------------- scatter: last-edge-wins per dense cell --------------------
__global__ void k_scatter(const int* __restrict__ er, const int* __restrict__ ec) {
    int k = blockIdx.x * blockDim.x + threadIdx.x;
    if (k < NE) atomicMax(&g_last[er[k] * NN + ec[k]], k);
}

// ---------------- amax of dense adj2 (cells with last-edge set; all >= 0) ---
__global__ void k_amax(const float* __restrict__ adj_vals) {
    __shared__ float sa[16];
    int idx = blockIdx.x * blockDim.x + threadIdx.x;   // 512 blocks x 512 thr
    int t = threadIdx.x, w = t >> 5, l = t & 31;
    float m = 0.f;
    int le = g_last[idx];
    if (le >= 0) m = 2.f * adj_vals[le];
    for (int o = 16; o > 0; o >>= 1) m = fmaxf(m, __shfl_xor_sync(0xffffffffu, m, o));
    if (l == 0) sa[w] = m;
    __syncthreads();
    if (t == 0) {
        float mm = 0.f;
        for (int i = 0; i < 16; i++) mm = fmaxf(mm, sa[i]);
        atomicMax(&g_amax, __float_as_uint(mm));
    }
}

// ---------------- bias2 partials: chunk rc of rho, 4 batch outputs ----------
__global__ void k_bias2(const float* __restrict__ W, const float* __restrict__ img) {
    int j  = blockIdx.x * 128 + threadIdx.x;   // grid.x = 8
    int rc = blockIdx.y;                       // 0..31
    int r0 = rc * 128;
    float a0 = 0.f, a1 = 0.f, a2 = 0.f, a3 = 0.f;
    #pragma unroll 4
    for (int rr = 0; rr < 128; rr++) {
        int rho = r0 + rr;
        float w = W[(size_t)rho * HD + j];
        int d = rho & 1023;
        a0 += img[d]        * w;
        a1 += img[1024 + d] * w;
        a2 += img[2048 + d] * w;
        a3 += img[3072 + d] * w;
    }
    g_b2part[(rc * 4 + 0) * HD + j] = a0;
    g_b2part[(rc * 4 + 1) * HD + j] = a1;
    g_b2part[(rc * 4 + 2) * HD + j] = a2;
    g_b2part[(rc * 4 + 3) * HD + j] = a3;
}

// ---------------- 64x128 SGEMM body, double-buffered, 4x8 micro -------------
// Thread map: 256 thr; ty=tid>>4 (4-row group), tx=tid&15 (cols {tx*4, 64+tx*4})
__device__ __forceinline__ void sgemm_64x128(
    const float* __restrict__ A, int lda,
    const float* __restrict__ B, int ldb,
    float* __restrict__ C, int ldc,
    int kBase, int kLen)
{
    __shared__ float As[2][16][68];    // transposed + padded (68 = 4 mod 32, 16B-aligned rows)
    __shared__ float Bs[2][16][128];
    const int tid = threadIdx.x;
    const int tx = tid & 15, ty = tid >> 4;
    const int brow = blockIdx.y * 64;
    const int bcol = blockIdx.x * 128;
    const int a_row = tid >> 2;          // 0..63
    const int a_col = (tid & 3) << 2;    // 0,4,8,12
    const int b_row = tid >> 4;          // 0..15
    const int b_col = (tid & 15) << 3;   // 0..120

    const float* Aptr = A + (size_t)(brow + a_row) * lda + kBase + a_col;
    const float* Bptr = B + (size_t)(kBase + b_row) * ldb + bcol + b_col;

    float4 av  = *reinterpret_cast<const float4*>(Aptr);
    float4 bv0 = *reinterpret_cast<const float4*>(Bptr);
    float4 bv1 = *reinterpret_cast<const float4*>(Bptr + 4);

    const int T = kLen >> 4;
    float acc[4][8] = {};

    As[0][a_col + 0][a_row] = av.x;
    As[0][a_col + 1][a_row] = av.y;
    As[0][a_col + 2][a_row] = av.z;
    As[0][a_col + 3][a_row] = av.w;
    *reinterpret_cast<float4*>(&Bs[0][b_row][b_col])     = bv0;
    *reinterpret_cast<float4*>(&Bs[0][b_row][b_col + 4]) = bv1;
    __syncthreads();

    int cur = 0;
    for (int t = 0; t < T; t++) {
        if (t + 1 < T) {
            av  = *reinterpret_cast<const float4*>(Aptr + (t + 1) * 16);
            bv0 = *reinterpret_cast<const float4*>(Bptr + (size_t)(t + 1) * 16 * ldb);
            bv1 = *reinterpret_cast<const float4*>(Bptr + (size_t)(t + 1) * 16 * ldb + 4);
        }
        #pragma unroll
        for (int k = 0; k < 16; k++) {
            float4 a4  = *reinterpret_cast<const float4*>(&As[cur][k][ty << 2]);
            float4 b4a = *reinterpret_cast<const float4*>(&Bs[cur][k][tx << 2]);
            float4 b4b = *reinterpret_cast<const float4*>(&Bs[cur][k][64 + (tx << 2)]);
            float ar[4] = {a4.x, a4.y, a4.z, a4.w};
            float br[8] = {b4a.x, b4a.y, b4a.z, b4a.w, b4b.x, b4b.y, b4b.z, b4b.w};
            #pragma unroll
            for (int i = 0; i < 4; i++)
                #pragma unroll
                for (int j = 0; j < 8; j++)
                    acc[i][j] += ar[i] * br[j];
        }
        if (t + 1 < T) {
            int nxt = cur ^ 1;
            As[nxt][a_col + 0][a_row] = av.x;
            As[nxt][a_col + 1][a_row] = av.y;
            As[nxt][a_col + 2][a_row] = av.z;
            As[nxt][a_col + 3][a_row] = av.w;
            *reinterpret_cast<float4*>(&Bs[nxt][b_row][b_col])     = bv0;
            *reinterpret_cast<float4*>(&Bs[nxt][b_row][b_col + 4]) = bv1;
            __syncthreads();
            cur = nxt;
        }
    }
    #pragma unroll
    for (int i = 0; i < 4; i++) {
        int r = brow + (ty << 2) + i;
        float4 o0, o1;
        o0.x = acc[i][0]; o0.y = acc[i][1]; o0.z = acc[i][2]; o0.w = acc[i][3];
        o1.x = acc[i][4]; o1.y = acc[i][5]; o1.z = acc[i][6]; o1.w = acc[i][7];
        *reinterpret_cast<float4*>(&C[(size_t)r * ldc + bcol + (tx << 2)])      = o0;
        *reinterpret_cast<float4*>(&C[(size_t)r * ldc + bcol + 64 + (tx << 2)]) = o1;
    }
}

// S partials: g_Spart[z] = Xr[:, z*256:(z+1)*256] @ W[z*256:(z+1)*256, :]
__global__ void __launch_bounds__(256) k_gemmS(const float* __restrict__ X, const float* __restrict__ W) {
    sgemm_64x128(X, 4096, W, HD, &g_Spart[(size_t)blockIdx.z * 128 * HD], HD,
                 blockIdx.z * (4096 / ZS), 4096 / ZS);
}

// hp = attC(512x144) @ Hmat(144x1024)
__global__ void __launch_bounds__(256) k_gemmHP() {
    sgemm_64x128(g_attC, KR, g_Hmat, HD, g_hp, HD, 0, KR);
}

// ---------------- fused: reduce split-K + bias2 -> Hmat row, dot with a -----
__global__ void __launch_bounds__(256) k_redrow(const float* __restrict__ avec) {
    __shared__ float red[8];
    int row = blockIdx.x;              // 0..131
    int t = threadIdx.x;               // 256: one float4 per thread covers the row
    float4 v = make_float4(0.f, 0.f, 0.f, 0.f);
    if (row < 128) {
        #pragma unroll
        for (int z = 0; z < ZS; z++) {
            float4 u = *reinterpret_cast<const float4*>(
                &g_Spart[(size_t)z * 128 * HD + (size_t)row * HD + (t << 2)]);
            v.x += u.x; v.y += u.y; v.z += u.z; v.w += u.w;
        }
    } else {
        int b = row - 128;
        #pragma unroll 8
        for (int r = 0; r < 32; r++) {
            float4 u = *reinterpret_cast<const float4*>(
                &g_b2part[(size_t)(r * 4 + b) * HD + (t << 2)]);
            v.x += u.x; v.y += u.y; v.z += u.z; v.w += u.w;
        }
    }
    *reinterpret_cast<float4*>(&g_Hmat[(size_t)row * HD + (t << 2)]) = v;
    float4 a1 = *reinterpret_cast<const float4*>(&avec[t << 2]);
    float4 a2 = *reinterpret_cast<const float4*>(&avec[HD + (t << 2)]);
    float p1 = v.x * a1.x + v.y * a1.y + v.z * a1.z + v.w * a1.w;
    float p2 = v.x * a2.x + v.y * a2.y + v.z * a2.z + v.w * a2.w;
    int w = t >> 5, l = t & 31;
    for (int o = 16; o > 0; o >>= 1) p1 += __shfl_xor_sync(0xffffffffu, p1, o);
    if (l == 0) red[w] = p1;
    __syncthreads();
    if (t == 0) { float s = 0; for (int i = 0; i < 8; i++) s += red[i]; g_SS1[row] = s; }
    __syncthreads();
    for (int o = 16; o > 0; o >>= 1) p2 += __shfl_xor_sync(0xffffffffu, p2, o);
    if (l == 0) red[w] = p2;
    __syncthreads();
    if (t == 0) { float s = 0; for (int i = 0; i < 8; i++) s += red[i]; g_SS2[row] = s; }
}

// ---------------- softmax row + attC fold + direct new_adj write ------------
__global__ void __launch_bounds__(512) k_softmax(const float* __restrict__ adj_vals,
                                                 float* __restrict__ outp) {
    __shared__ float sw[16];       // per-warp p-sums (kept for batch fold)
    __shared__ float sa[16];
    __shared__ float sh[NN];
    __shared__ float s_m, s_Z;
    int n = blockIdx.x, c = threadIdx.x;   // 512 threads
    int w = c >> 5, l = c & 31;
    int le = g_last[n * NN + c];
    float s1n = g_SS1[n & 127] + g_SS1[128 + (n >> 7)];
    float ev = 0.f, adv = 0.f;
    if (le >= 0) {
        float x = s1n + g_SS2[c & 127] + g_SS2[128 + (c >> 7)];
        ev = (x > 0.f) ? x : 0.2f * x;     // leaky_relu 0.2
        adv = 2.f * adj_vals[le];
    }
    // row max
    float r = ev;
    for (int o = 16; o > 0; o >>= 1) r = fmaxf(r, __shfl_xor_sync(0xffffffffu, r, o));
    if (l == 0) sa[w] = r;
    __syncthreads();
    if (w == 0) {
        float m = sa[l & 15];
        for (int o = 8; o > 0; o >>= 1) m = fmaxf(m, __shfl_xor_sync(0xffffffffu, m, o));
        if (l == 0) s_m = m;
    }
    __syncthreads();
    float p = expf(ev - s_m);
    // row sum
    r = p;
    for (int o = 16; o > 0; o >>= 1) r += __shfl_xor_sync(0xffffffffu, r, o);
    if (l == 0) sw[w] = r;
    __syncthreads();
    if (w == 0) {
        float z = (l < 16) ? sw[l] : 0.f;
        for (int o = 16; o > 0; o >>= 1) z += __shfl_xor_sync(0xffffffffu, z, o);
        if (l == 0) s_Z = z;
    }
    __syncthreads();
    float invZ = 1.f / s_Z;
    float att = p * invZ;
    float invA = 1.f / __uint_as_float(g_amax);
    outp[n * NN + c] = att * adv * invA;   // new_adj directly (amin == 0 structurally)
    sh[c] = att;
    __syncthreads();
    if (c < 128) {
        g_attC[(size_t)n * KR + c] = sh[c] + sh[c + 128] + sh[c + 256] + sh[c + 384];
    } else if (c < 132) {
        int b = c - 128;
        g_attC[(size_t)n * KR + c] = (sw[4 * b] + sw[4 * b + 1] + sw[4 * b + 2] + sw[4 * b + 3]) * invZ;
    } else if (c < KR) {
        g_attC[(size_t)n * KR + c] = 0.f;
    }
}

// ---------------- out partials: lin_w[i,:] . hp_flat  (HBM-bound, 1.08 GB) --
__global__ void __launch_bounds__(256) k_matvec(const float* __restrict__ lin_w) {
    __shared__ float red[8];
    int i   = blockIdx.y;              // 0..512
    int seg = blockIdx.x;              // 0..15
    const int SEG = (NN * HD) / 16;    // 32768
    size_t base = (size_t)i * (NN * HD) + (size_t)seg * SEG;
    const float4* wp4 = reinterpret_cast<const float4*>(lin_w + base);
    const float4* vp4 = reinterpret_cast<const float4*>(g_hp + seg * SEG);
    int t = threadIdx.x;               // 256
    float s = 0.f;
    #pragma unroll 8
    for (int idx = t; idx < SEG / 4; idx += 256) {
        float4 w = __ldcs(wp4 + idx);      // streaming: keep hp resident in L2
        float4 v = vp4[idx];
        s += w.x * v.x + w.y * v.y + w.z * v.z + w.w * v.w;
    }
    for (int o = 16; o > 0; o >>= 1) s += __shfl_down_sync(0xffffffffu, s, o);
    if ((t & 31) == 0) red[t >> 5] = s;
    __syncthreads();
    if (t == 0) {
        float tot = 0.f;
        for (int w = 0; w < 8; w++) tot += red[w];
        g_outpart[i * 16 + seg] = tot;
    }
}

// ---------------- final: sum partials, min-max normalize 513 outputs --------
__global__ void k_final(const float* __restrict__ lin_b, float* __restrict__ outp) {
    __shared__ float red[16];
    __shared__ float s_mn, s_mx;
    int t = threadIdx.x;               // 512 threads
    float v0 = lin_b[t];
    #pragma unroll
    for (int s = 0; s < 16; s++) v0 += g_outpart[t * 16 + s];
    bool has2 = (t == 0);
    float v1 = 0.f;
    if (has2) {
        v1 = lin_b[NN];
        for (int s = 0; s < 16; s++) v1 += g_outpart[NN * 16 + s];
    }
    float mn = v0, mx = v0;
    if (has2) { mn = fminf(mn, v1); mx = fmaxf(mx, v1); }
    float r = mn;
    for (int o = 16; o > 0; o >>= 1) r = fminf(r, __shfl_down_sync(0xffffffffu, r, o));
    if ((t & 31) == 0) red[t >> 5] = r;
    __syncthreads();
    if (t < 32) {
        r = (t < 16) ? red[t] : red[0];
        for (int o = 8; o > 0; o >>= 1) r = fminf(r, __shfl_down_sync(0xffffffffu, r, o));
        if (t == 0) s_mn = r;
    }
    __syncthreads();
    r = mx;
    for (int o = 16; o > 0; o >>= 1) r = fmaxf(r, __shfl_down_sync(0xffffffffu, r, o));
    if ((t & 31) == 0) red[t >> 5] = r;
    __syncthreads();
    if (t < 32) {
        r = (t < 16) ? red[t] : red[0];
        for (int o = 8; o > 0; o >>= 1) r = fmaxf(r, __shfl_down_sync(0xffffffffu, r, o));
        if (t == 0) s_mx = r;
    }
    __syncthreads();
    float mnv = s_mn;
    float den = s_mx - s_mn;
    if (den == 0.f) {
        outp[t] = 0.5f;
        if (has2) outp[NN] = 0.5f;
    } else {
        outp[t] = (v0 - mnv) / den;
        if (has2) outp[NN] = (v1 - mnv) / den;
    }
}

// ---------------- launcher ---------------------------------------------------
extern "C" void kernel_launch(void* const* d_in, const int* in_sizes, int n_in,
                              void* d_out, int out_size) {
    (void)in_sizes; (void)n_in; (void)out_size;
    const float* img   = (const float*)d_in[0];   // (4,1024)
    const int*   erow  = (const int*)  d_in[1];   // (16384,)
    const int*   ecol  = (const int*)  d_in[2];   // (16384,)
    const float* adjv  = (const float*)d_in[3];   // (16384,)
    const float* X     = (const float*)d_in[4];   // (512,1024)
    const float* W     = (const float*)d_in[5];   // (4096,1024)
    const float* avec  = (const float*)d_in[6];   // (2048,1)
    const float* linw  = (const float*)d_in[7];   // (513, 524288)
    const float* linb  = (const float*)d_in[8];   // (513,)
    float* out = (float*)d_out;                   // 262144 new_adj + 513 normalized

    void* p_last = nullptr;  cudaGetSymbolAddress(&p_last, g_last);
    void* p_amax = nullptr;  cudaGetSymbolAddress(&p_amax, g_amax);
    cudaMemsetAsync(p_last, 0xFF, (size_t)NN * NN * sizeof(int), 0);  // -1
    cudaMemsetAsync(p_amax, 0x00, sizeof(unsigned), 0);

    k_scatter<<<64, 256>>>(erow, ecol);
    k_amax<<<512, 512>>>(adjv);
    k_bias2<<<dim3(8, 32), 128>>>(W, img);
    k_gemmS<<<dim3(8, 2, ZS), 256>>>(X, W);
    k_redrow<<<132, 256>>>(avec);
    k_softmax<<<NN, NN>>>(adjv, out);
    k_gemmHP<<<dim3(8, 8, 1), 256>>>();
    k_matvec<<<dim3(16, NN + 1), 256>>>(linw);
    k_final<<<1, NN>>>(linb, out + NN * NN);
}